// round 9
// baseline (speedup 1.0000x reference)
#include <cuda_runtime.h>
#include <math.h>

// ---------------- problem constants ----------------
#define NMAX        16384
#define MMAX        4096
#define BINS_TOTAL  65536
#define BIN_OFFSET  24576
#define NORM_F      0.8932438417380023f   // (2/pi)^0.25

// ---------------- device scratch (statically zero-initialized; each kernel
// resets what it consumed so graph replays see a clean state) ----------------
static __device__ float  g_wpsi[MMAX];        // trapz weight * psi
static __device__ int    g_pres[BINS_TOTAL];  // presence (0/1); zeroed by k_scan pass 2
static __device__ int    g_rank[BINS_TOTAL];  // rank among sorted unique bins
static __device__ float2 g_vals[NMAX];        // pref * factors (complex)
static __device__ int    g_binoff[NMAX];
static __device__ float2 g_binned[NMAX];      // zeroed by k_scan each call
static __device__ float  g_qc[NMAX];
static __device__ float  g_pc[NMAX];
static __device__ float  g_loss;              // reset by last k_gt_loss block
static __device__ unsigned int g_done;        // atomicInc wraps -> self-resetting

// ---------------- K1: binning + prefactor + trapz weights ----------------
__global__ void k_prep(const float* __restrict__ fre, const float* __restrict__ fim,
                       const float* __restrict__ qre, const float* __restrict__ qim,
                       const float* __restrict__ pre, const float* __restrict__ pim,
                       const float* __restrict__ x,   const float* __restrict__ psi,
                       int N, int M) {
    int j = blockIdx.x * blockDim.x + threadIdx.x;
    if (j < M) {                              // trapz weight * psi
        float w;
        if (M < 2)           w = 0.f;
        else if (j == 0)     w = 0.5f * (x[1] - x[0]);
        else if (j == M - 1) w = 0.5f * (x[M-1] - x[M-2]);
        else                 w = 0.5f * (x[j+1] - x[j-1]);
        g_wpsi[j] = w * psi[j];
    }
    if (j >= N) return;

    float qf = qre[j] - 0.5f * pim[j];           // Re(xi)/(2g)
    float pf = 2.0f * qim[j] + pre[j];           // Im(xi)

    // dq = 0.125 (exact), dp = 0.15625 (exact). IEEE divides so floor matches
    // jnp bit-exactly at bin boundaries (a flipped bin moves an O(100) value).
    float qb = floorf(__fdiv_rn(qf - (-8.0f),  0.125f));
    float pb = floorf(__fdiv_rn(pf - (-10.0f), 0.15625f));

    int bin = (int)(qb * 128.0f + pb);           // trunc like astype(int32)
    int off = bin + BIN_OFFSET;
    off = min(max(off, 0), BINS_TOTAL - 1);
    g_pres[off]  = 1;
    g_binoff[j]  = off;

    g_qc[j] = (qb + 0.5f) * 0.125f   + (-8.0f);
    g_pc[j] = (pb + 0.5f) * 0.15625f + (-10.0f);

    float qi  = qim[j];
    float prf = NORM_F * expf(qi * qi);
    float s, c;
    sincosf(pre[j] * qi, &s, &c);                // accurate: only 16K calls
    float prRe = fminf(fmaxf(prf * c, -100.0f), 100.0f);
    float prIm = fminf(fmaxf(prf * s, -100.0f), 100.0f);

    float fr = fre[j], fi = fim[j];
    g_vals[j] = make_float2(prRe * fr - prIm * fi,
                            prRe * fi + prIm * fr);
}

// ---------------- K2: ballot-based exclusive scan, coalesced, self-cleaning ----
__global__ void __launch_bounds__(1024) k_scan(int N) {
    const int tid  = threadIdx.x;
    const int warp = tid >> 5, lane = tid & 31;
    const unsigned FULL = 0xffffffffu;
    const unsigned ltmask = (1u << lane) - 1u;
    const int base = warp * 2048;

    __shared__ int wtot[32], woff[32];

    int cnt = 0;
    #pragma unroll 4
    for (int k = 0; k < 64; k++) {
        int p = g_pres[base + k * 32 + lane];
        unsigned mask = __ballot_sync(FULL, p != 0);
        cnt += __popc(mask);
    }
    if (lane == 0) wtot[warp] = cnt;
    __syncthreads();

    if (warp == 0) {
        int v = wtot[lane];
        int inc = v;
        #pragma unroll
        for (int o = 1; o < 32; o <<= 1) {
            int n = __shfl_up_sync(FULL, inc, o);
            if (lane >= o) inc += n;
        }
        woff[lane] = inc - v;
    }
    __syncthreads();

    int running = woff[warp];
    #pragma unroll 4
    for (int k = 0; k < 64; k++) {
        int idx = base + k * 32 + lane;
        int p = g_pres[idx];
        unsigned mask = __ballot_sync(FULL, p != 0);
        g_rank[idx] = running + __popc(mask & ltmask);
        g_pres[idx] = 0;                     // self-clean for next call
        running += __popc(mask);
    }

    for (int i = tid; i < N; i += 1024)
        g_binned[i] = make_float2(0.f, 0.f);
}

// ---------------- K3: scatter-add vals into compacted bins ----------------
__global__ void k_scatter(int N) {
    int j = blockIdx.x * blockDim.x + threadIdx.x;
    if (j >= N) return;
    int ind = g_rank[g_binoff[j]];
    float2 v = g_vals[j];
    atomicAdd(&g_binned[ind].x, v.x);
    atomicAdd(&g_binned[ind].y, v.y);
}

// ---------------- K4: gt = trapz(conj(gf)*psi) via FMA recurrences, fused loss
// One warp per trajectory. Uniform grid => Gaussian follows e*=u, u*=w and the
// phase is a constant-angle rotation; the inner loop is MUFU-free.
__global__ void __launch_bounds__(128) k_gt_loss(const float* __restrict__ x,
                                                 float* __restrict__ out,
                                                 int M, int N, int nblocks) {
    __shared__ float sred[4];
    const int tid  = threadIdx.x;
    const int warp = tid >> 5, lane = tid & 31;
    const int j = blockIdx.x * 4 + warp;

    float contrib = 0.f;
    if (j < N && M >= 2) {
        const float qc = g_qc[j], pc = g_pc[j];

        // High-accuracy lane-stride: Delta = 32h from double endpoints
        // (fp32 x[1]-x[0] carries ~1e-6 error -> 0.016 rad cumulative drift;
        //  double endpoints give ~1e-8 -> negligible).
        const float x0 = x[0];
        const double hd = ((double)x[M - 1] - (double)x0) / (double)(M - 1);
        const float h  = (float)hd;
        const float D  = (float)(32.0 * hd);      // lane stride in x

        int lo = (int)((qc - 8.0f - x0) / h);       lo = max(lo, 0);
        int hi = (int)((qc + 8.0f - x0) / h) + 2;   hi = min(hi, M);

        float ar = 0.f, ai = 0.f;
        int m = lo + lane;
        if (m < hi) {
            // per-lane inits from the ACTUAL grid point (accurate intrinsics)
            float dx0 = x[m] - qc;
            float e   = expf(-dx0 * dx0);
            float u   = expf(-(2.0f * D * dx0 + D * D));   // e_{k+1}/e_k at k=0
            const float w = expf(-2.0f * D * D);           // u_{k+1}/u_k (const)
            float cA, sA;                                  // (cos, -sin) of pc*dx
            {
                float s0, c0;
                sincosf(pc * dx0, &s0, &c0);
                cA = c0; sA = -s0;                         // conj phase
            }
            float cs, sn;                                  // rotation by phi = pc*D
            sincosf(pc * D, &sn, &cs);

            #pragma unroll 2
            for (; m < hi; m += 32) {
                float t = e * __ldg(&g_wpsi[m]);
                ar = fmaf(t, cA, ar);
                ai = fmaf(t, sA, ai);
                // rotate (cA, sA): theta += phi with sA = -sin convention
                float tc = sA * sn;
                float ts = cA * sn;
                float cN = fmaf(cA, cs, tc);
                sA = fmaf(sA, cs, -ts);
                cA = cN;
                e *= u;
                u *= w;
            }
        }
        #pragma unroll
        for (int o = 16; o; o >>= 1) {
            ar += __shfl_down_sync(0xffffffffu, ar, o);
            ai += __shfl_down_sync(0xffffffffu, ai, o);
        }
        if (lane == 0) {
            float gtr = NORM_F * ar, gti = NORM_F * ai;
            float2 b = g_binned[j];
            float dr = b.x - gtr, di = b.y - gti;
            contrib = dr * dr + di * di;
        }
    }
    if (lane == 0) sred[warp] = contrib;
    __syncthreads();

    if (tid == 0) {
        float t = sred[0] + sred[1] + sred[2] + sred[3];
        atomicAdd(&g_loss, t);
        __threadfence();
        unsigned int prev = atomicInc(&g_done, (unsigned int)(nblocks - 1));
        if (prev == (unsigned int)(nblocks - 1)) {
            float total = atomicAdd(&g_loss, 0.0f);   // L2-coherent read
            out[0] = sqrtf(total);
            atomicExch(&g_loss, 0.0f);                // reset for next replay
        }
    }
}

// ---------------- launch (4 kernels) ----------------
extern "C" void kernel_launch(void* const* d_in, const int* in_sizes, int n_in,
                              void* d_out, int out_size) {
    const float* fre = (const float*)d_in[0];
    const float* fim = (const float*)d_in[1];
    const float* qre = (const float*)d_in[2];
    const float* qim = (const float*)d_in[3];
    const float* pre = (const float*)d_in[4];
    const float* pim = (const float*)d_in[5];
    const float* x   = (const float*)d_in[6];
    const float* psi = (const float*)d_in[7];

    int N = in_sizes[0];
    int M = in_sizes[6];
    if (N > NMAX) N = NMAX;
    if (M > MMAX) M = MMAX;

    int nb = (N + 3) / 4;
    k_prep   <<<(N + 255) / 256, 256>>>(fre, fim, qre, qim, pre, pim, x, psi, N, M);
    k_scan   <<<1, 1024>>>(N);
    k_scatter<<<(N + 255) / 256, 256>>>(N);
    k_gt_loss<<<nb, 128>>>(x, (float*)d_out, M, N, nb);
}

// round 10
// speedup vs baseline: 1.5820x; 1.5820x over previous
#include <cuda_runtime.h>
#include <math.h>

// ---------------- problem constants ----------------
#define NMAX        16384
#define MMAX        4096
#define BINS_TOTAL  65536
#define NWORDS      2048              // BINS_TOTAL / 32
#define BIN_OFFSET  24576
#define NORM_F      0.8932438417380023f   // (2/pi)^0.25

// ---------------- device scratch (statically zero-initialized; each kernel
// resets what it consumed so graph replays see a clean state) ----------------
static __device__ float    g_wpsi[MMAX];      // trapz weight * psi
static __device__ unsigned g_bits[NWORDS];    // presence bitmask; zeroed by k_gt_loss
static __device__ int      g_wordpfx[NWORDS]; // exclusive popc prefix per word
static __device__ float2   g_vals[NMAX];      // pref * factors (complex)
static __device__ int      g_binoff[NMAX];
static __device__ float2   g_binned[NMAX];    // zeroed by k_prep each call
static __device__ float    g_qc[NMAX];
static __device__ float    g_pc[NMAX];
static __device__ float    g_loss;            // reset by last k_gt_loss block
static __device__ unsigned int g_done;        // atomicInc wraps -> self-resetting

// ---------------- K1: binning + prefactor + trapz weights + binned zero ------
__global__ void k_prep(const float* __restrict__ fre, const float* __restrict__ fim,
                       const float* __restrict__ qre, const float* __restrict__ qim,
                       const float* __restrict__ pre, const float* __restrict__ pim,
                       const float* __restrict__ x,   const float* __restrict__ psi,
                       int N, int M) {
    int j = blockIdx.x * blockDim.x + threadIdx.x;
    if (j < M) {                              // trapz weight * psi
        float w;
        if (M < 2)           w = 0.f;
        else if (j == 0)     w = 0.5f * (x[1] - x[0]);
        else if (j == M - 1) w = 0.5f * (x[M-1] - x[M-2]);
        else                 w = 0.5f * (x[j+1] - x[j-1]);
        g_wpsi[j] = w * psi[j];
    }
    if (j >= N) return;

    g_binned[j] = make_float2(0.f, 0.f);      // consumed by scatter/gt this call

    float qf = qre[j] - 0.5f * pim[j];           // Re(xi)/(2g)
    float pf = 2.0f * qim[j] + pre[j];           // Im(xi)

    // dq = 0.125 (exact), dp = 0.15625 (exact). IEEE divides so floor matches
    // jnp bit-exactly at bin boundaries (a flipped bin moves an O(100) value).
    float qb = floorf(__fdiv_rn(qf - (-8.0f),  0.125f));
    float pb = floorf(__fdiv_rn(pf - (-10.0f), 0.15625f));

    int bin = (int)(qb * 128.0f + pb);           // trunc like astype(int32)
    int off = bin + BIN_OFFSET;
    off = min(max(off, 0), BINS_TOTAL - 1);
    atomicOr(&g_bits[off >> 5], 1u << (off & 31));
    g_binoff[j] = off;

    g_qc[j] = (qb + 0.5f) * 0.125f   + (-8.0f);
    g_pc[j] = (pb + 0.5f) * 0.15625f + (-10.0f);

    float qi  = qim[j];
    float prf = NORM_F * expf(qi * qi);
    float s, c;
    sincosf(pre[j] * qi, &s, &c);                // accurate: only 16K calls
    float prRe = fminf(fmaxf(prf * c, -100.0f), 100.0f);
    float prIm = fminf(fmaxf(prf * s, -100.0f), 100.0f);

    float fr = fre[j], fi = fim[j];
    g_vals[j] = make_float2(prRe * fr - prIm * fi,
                            prRe * fi + prIm * fr);
}

// ---------------- K2: popc prefix over 2048 bitmask words (1 block) ----------
__global__ void __launch_bounds__(1024) k_scan() {
    const int t = threadIdx.x;
    const int warp = t >> 5, lane = t & 31;
    const unsigned FULL = 0xffffffffu;

    unsigned w0 = g_bits[2 * t], w1 = g_bits[2 * t + 1];
    int c0 = __popc(w0), c1 = __popc(w1);
    int sum = c0 + c1;

    // warp inclusive scan of per-thread sums
    int inc = sum;
    #pragma unroll
    for (int o = 1; o < 32; o <<= 1) {
        int v = __shfl_up_sync(FULL, inc, o);
        if (lane >= o) inc += v;
    }

    __shared__ int wtot[32], woff[32];
    if (lane == 31) wtot[warp] = inc;
    __syncthreads();
    if (warp == 0) {
        int v = wtot[lane];
        int i2 = v;
        #pragma unroll
        for (int o = 1; o < 32; o <<= 1) {
            int n = __shfl_up_sync(FULL, i2, o);
            if (lane >= o) i2 += n;
        }
        woff[lane] = i2 - v;
    }
    __syncthreads();

    int excl = inc - sum + woff[warp];        // exclusive prefix for word 2t
    g_wordpfx[2 * t]     = excl;
    g_wordpfx[2 * t + 1] = excl + c0;
}

// ---------------- K3: scatter-add vals into compacted bins -------------------
__global__ void k_scatter(int N) {
    int j = blockIdx.x * blockDim.x + threadIdx.x;
    if (j >= N) return;
    int off = g_binoff[j];
    int w = off >> 5, b = off & 31;
    int ind = g_wordpfx[w] + __popc(g_bits[w] & ((1u << b) - 1u));
    float2 v = g_vals[j];
    atomicAdd(&g_binned[ind].x, v.x);
    atomicAdd(&g_binned[ind].y, v.y);
}

// ---------------- K4: gt = trapz(conj(gf)*psi) via FMA recurrences, fused loss
// One warp per trajectory. Uniform grid => Gaussian follows e*=u, u*=w and the
// phase is a constant-angle rotation; the inner loop is MUFU-free.
__global__ void __launch_bounds__(128) k_gt_loss(const float* __restrict__ x,
                                                 float* __restrict__ out,
                                                 int M, int N, int nblocks) {
    __shared__ float sred[4];
    const int tid  = threadIdx.x;
    const int warp = tid >> 5, lane = tid & 31;
    const int j = blockIdx.x * 4 + warp;

    // first 16 blocks re-zero the presence bitmask for the next replay
    // (its last reader was k_scatter; no one reads it in this kernel)
    if (blockIdx.x < 16 && tid < 128) g_bits[blockIdx.x * 128 + tid] = 0u;

    float contrib = 0.f;
    if (j < N && M >= 2) {
        const float qc = g_qc[j], pc = g_pc[j];

        // High-accuracy lane-stride: Delta = 32h from double endpoints
        // (fp32 x[1]-x[0] carries ~1e-6 error -> cumulative phase drift).
        const float x0 = x[0];
        const double hd = ((double)x[M - 1] - (double)x0) / (double)(M - 1);
        const float h  = (float)hd;
        const float D  = (float)(32.0 * hd);      // lane stride in x

        // support window +-6: truncation residual exp(-36)*w*psi ~ 1e-17
        int lo = (int)((qc - 6.0f - x0) / h);       lo = max(lo, 0);
        int hi = (int)((qc + 6.0f - x0) / h) + 2;   hi = min(hi, M);

        float ar = 0.f, ai = 0.f;
        int m = lo + lane;
        if (m < hi) {
            // per-lane inits from the ACTUAL grid point; fast intrinsics are
            // safe here: init errors (~3e-7) scale results, don't compound
            // beyond ~k*ulp over the 37-iteration window.
            float dx0 = x[m] - qc;
            float e   = __expf(-dx0 * dx0);
            float u   = __expf(-(2.0f * D * dx0 + D * D));  // e_{k+1}/e_k at k=0
            const float w = __expf(-2.0f * D * D);          // u_{k+1}/u_k (const)
            float cA, sA;                                   // (cos, -sin) of pc*dx
            {
                float s0, c0;
                __sincosf(pc * dx0, &s0, &c0);
                cA = c0; sA = -s0;                          // conj phase
            }
            float cs, sn;                                   // rotation by phi = pc*D
            __sincosf(pc * D, &sn, &cs);

            #pragma unroll 2
            for (; m < hi; m += 32) {
                float t = e * __ldg(&g_wpsi[m]);
                ar = fmaf(t, cA, ar);
                ai = fmaf(t, sA, ai);
                // rotate (cA, sA): theta += phi with sA = -sin convention
                float tc = sA * sn;
                float ts = cA * sn;
                float cN = fmaf(cA, cs, tc);
                sA = fmaf(sA, cs, -ts);
                cA = cN;
                e *= u;
                u *= w;
            }
        }
        #pragma unroll
        for (int o = 16; o; o >>= 1) {
            ar += __shfl_down_sync(0xffffffffu, ar, o);
            ai += __shfl_down_sync(0xffffffffu, ai, o);
        }
        if (lane == 0) {
            float gtr = NORM_F * ar, gti = NORM_F * ai;
            float2 b = g_binned[j];
            float dr = b.x - gtr, di = b.y - gti;
            contrib = dr * dr + di * di;
        }
    }
    if (lane == 0) sred[warp] = contrib;
    __syncthreads();

    if (tid == 0) {
        float t = sred[0] + sred[1] + sred[2] + sred[3];
        atomicAdd(&g_loss, t);
        __threadfence();
        unsigned int prev = atomicInc(&g_done, (unsigned int)(nblocks - 1));
        if (prev == (unsigned int)(nblocks - 1)) {
            float total = atomicAdd(&g_loss, 0.0f);   // L2-coherent read
            out[0] = sqrtf(total);
            atomicExch(&g_loss, 0.0f);                // reset for next replay
        }
    }
}

// ---------------- launch (4 kernels) ----------------
extern "C" void kernel_launch(void* const* d_in, const int* in_sizes, int n_in,
                              void* d_out, int out_size) {
    const float* fre = (const float*)d_in[0];
    const float* fim = (const float*)d_in[1];
    const float* qre = (const float*)d_in[2];
    const float* qim = (const float*)d_in[3];
    const float* pre = (const float*)d_in[4];
    const float* pim = (const float*)d_in[5];
    const float* x   = (const float*)d_in[6];
    const float* psi = (const float*)d_in[7];

    int N = in_sizes[0];
    int M = in_sizes[6];
    if (N > NMAX) N = NMAX;
    if (M > MMAX) M = MMAX;

    int nb = (N + 3) / 4;
    k_prep   <<<(N + 255) / 256, 256>>>(fre, fim, qre, qim, pre, pim, x, psi, N, M);
    k_scan   <<<1, 1024>>>();
    k_scatter<<<(N + 255) / 256, 256>>>(N);
    k_gt_loss<<<nb, 128>>>(x, (float*)d_out, M, N, nb);
}

// round 13
// speedup vs baseline: 1.7879x; 1.1301x over previous
#include <cuda_runtime.h>
#include <math.h>

// ---------------- problem constants ----------------
#define NMAX        16384
#define MMAX        4096
#define BINS_TOTAL  65536
#define NWORDS      2048              // BINS_TOTAL / 32
#define BIN_OFFSET  24576
#define NORM_F      0.8932438417380023f   // (2/pi)^0.25
#define GT_BLOCKS   1776              // 148 SMs * 12 blocks, one wave

// ---------------- device scratch (statically zero-initialized; each kernel
// resets what it consumed so graph replays see a clean state) ----------------
static __device__ float    g_wpsi[MMAX];      // trapz weight * psi
static __device__ unsigned g_bits[NWORDS];    // presence bitmask; zeroed by k_gt_loss
static __device__ float2   g_vals[NMAX];      // pref * factors (complex)
static __device__ int      g_binoff[NMAX];
static __device__ float2   g_binned[NMAX];    // zeroed by k_prep each call
static __device__ float    g_qc[NMAX];
static __device__ float    g_pc[NMAX];
static __device__ float2   g_rot[NMAX];       // (cos, sin) of pc*D (accurate)
static __device__ float    g_D, g_invh, g_wc; // lane stride, 1/h, exp(-2D^2)
static __device__ float    g_loss;            // reset by last k_gt_loss block
static __device__ unsigned int g_done;        // atomicInc wraps -> self-resetting

// ---------------- K1: binning + prefactor + weights + constants --------------
__global__ void k_prep(const float* __restrict__ fre, const float* __restrict__ fim,
                       const float* __restrict__ qre, const float* __restrict__ qim,
                       const float* __restrict__ pre, const float* __restrict__ pim,
                       const float* __restrict__ x,   const float* __restrict__ psi,
                       int N, int M) {
    int j = blockIdx.x * blockDim.x + threadIdx.x;
    if (j < M) {                              // trapz weight * psi
        float w;
        if (M < 2)           w = 0.f;
        else if (j == 0)     w = 0.5f * (x[1] - x[0]);
        else if (j == M - 1) w = 0.5f * (x[M-1] - x[M-2]);
        else                 w = 0.5f * (x[j+1] - x[j-1]);
        g_wpsi[j] = w * psi[j];
    }
    if (j >= N) return;

    g_binned[j] = make_float2(0.f, 0.f);      // consumed by scatter/gt this call

    // grid constants in double ONCE here (cheap: 64 blocks); k_gt_loss must
    // stay FP64-free (DP pipe rt ~18.4 cyc/SM would throttle it).
    const double hd = (M >= 2)
        ? ((double)x[M - 1] - (double)x[0]) / (double)(M - 1) : 1.0;
    const float D = (float)(32.0 * hd);
    if (j == 0) {
        g_D    = D;
        g_invh = (float)(1.0 / hd);
        g_wc   = expf(-2.0f * D * D);
    }

    float qf = qre[j] - 0.5f * pim[j];           // Re(xi)/(2g)
    float pf = 2.0f * qim[j] + pre[j];           // Im(xi)

    // dq = 0.125 (exact), dp = 0.15625 (exact). IEEE divides so floor matches
    // jnp bit-exactly at bin boundaries (a flipped bin moves an O(100) value).
    float qb = floorf(__fdiv_rn(qf - (-8.0f),  0.125f));
    float pb = floorf(__fdiv_rn(pf - (-10.0f), 0.15625f));

    int bin = (int)(qb * 128.0f + pb);           // trunc like astype(int32)
    int off = bin + BIN_OFFSET;
    off = min(max(off, 0), BINS_TOTAL - 1);
    atomicOr(&g_bits[off >> 5], 1u << (off & 31));
    g_binoff[j] = off;

    float qc = (qb + 0.5f) * 0.125f   + (-8.0f);
    float pc = (pb + 0.5f) * 0.15625f + (-10.0f);
    g_qc[j] = qc;
    g_pc[j] = pc;

    {   // per-trajectory rotation constant, accurate
        float s, c;
        sincosf(pc * D, &s, &c);
        g_rot[j] = make_float2(c, s);
    }

    float qi  = qim[j];
    float prf = NORM_F * expf(qi * qi);
    float s, c;
    sincosf(pre[j] * qi, &s, &c);                // accurate: only 16K calls
    float prRe = fminf(fmaxf(prf * c, -100.0f), 100.0f);
    float prIm = fminf(fmaxf(prf * s, -100.0f), 100.0f);

    float fr = fre[j], fi = fim[j];
    g_vals[j] = make_float2(prRe * fr - prIm * fi,
                            prRe * fi + prIm * fr);
}

// ---------------- K2: scatter-add with redundant in-block popc prefix --------
// Every block rebuilds the 2048-word rank prefix in shared (8KB bits + 8KB
// prefix, ~1K cycles) -- cheaper than a separate scan kernel + launch.
__global__ void __launch_bounds__(256) k_scatter(int N) {
    __shared__ unsigned sbits[NWORDS];
    __shared__ int      spfx[NWORDS];
    __shared__ int      wsum[8];
    const int tid  = threadIdx.x;
    const int lane = tid & 31, warp = tid >> 5;
    const unsigned FULL = 0xffffffffu;

    for (int i = tid; i < NWORDS; i += 256) sbits[i] = g_bits[i];
    __syncthreads();

    const int base = tid * 8;                 // each thread owns 8 words
    int c[8], sum = 0;
    #pragma unroll
    for (int k = 0; k < 8; k++) { c[k] = __popc(sbits[base + k]); sum += c[k]; }

    int inc = sum;                            // warp inclusive scan
    #pragma unroll
    for (int o = 1; o < 32; o <<= 1) {
        int v = __shfl_up_sync(FULL, inc, o);
        if (lane >= o) inc += v;
    }
    if (lane == 31) wsum[warp] = inc;
    __syncthreads();
    if (warp == 0 && lane < 8) {              // scan 8 warp totals
        int v = wsum[lane], i2 = v;
        #pragma unroll
        for (int o = 1; o < 8; o <<= 1) {
            int n = __shfl_up_sync(0xffu, i2, o);
            if (lane >= o) i2 += n;
        }
        wsum[lane] = i2 - v;
    }
    __syncthreads();

    int excl = inc - sum + wsum[warp];        // exclusive prefix for word base
    #pragma unroll
    for (int k = 0; k < 8; k++) { spfx[base + k] = excl; excl += c[k]; }
    __syncthreads();

    int j = blockIdx.x * 256 + tid;
    if (j >= N) return;
    int off = g_binoff[j];
    int w = off >> 5, b = off & 31;
    int ind = spfx[w] + __popc(sbits[w] & ((1u << b) - 1u));
    float2 v = g_vals[j];
    atomicAdd(&g_binned[ind].x, v.x);
    atomicAdd(&g_binned[ind].y, v.y);
}

// ---------------- K3: gt = trapz(conj(gf)*psi), complex recurrence, fused loss
// Grid-stride, one warp per trajectory. z = e*exp(-i*pc*dx) evolves by
// z *= r, r *= wc -- 8 fma-pipe ops per point, zero MUFU, zero FP64.
__global__ void __launch_bounds__(128) k_gt_loss(const float* __restrict__ x,
                                                 float* __restrict__ out,
                                                 int M, int N) {
    __shared__ float sred[4];
    const int tid  = threadIdx.x;
    const int warp = tid >> 5, lane = tid & 31;

    // first 16 blocks re-zero the presence bitmask for the next replay
    if (blockIdx.x < 16) g_bits[blockIdx.x * 128 + tid] = 0u;

    float acc = 0.f;
    if (M >= 2) {
        const float x0   = x[0];
        const float D    = g_D;
        const float invh = g_invh;
        const float wc   = g_wc;
        const float D2   = D * D;
        const float twoD = 2.0f * D;

        for (int j = blockIdx.x * 4 + warp; j < N; j += GT_BLOCKS * 4) {
            const float qc = g_qc[j], pc = g_pc[j];
            const float2 rot = g_rot[j];

            // support window +-6: truncation residual exp(-36)*w*psi ~ 1e-17
            int lo = (int)((qc - 6.0f - x0) * invh);       lo = max(lo, 0);
            int hi = (int)((qc + 6.0f - x0) * invh) + 2;   hi = min(hi, M);

            float ar = 0.f, ai = 0.f;
            int m = lo + lane;
            if (m < hi) {
                float dx0 = x[m] - qc;
                float e   = __expf(-dx0 * dx0);
                float u   = __expf(-fmaf(twoD, dx0, D2));  // e_{k+1}/e_k at k=0
                float s0, c0;
                __sincosf(pc * dx0, &s0, &c0);
                float zr = e * c0,  zi = -e * s0;          // e * exp(-i pc dx)
                float rr = u * rot.x, ri = -u * rot.y;     // u * exp(-i pc D)

                #pragma unroll 2
                for (; m < hi; m += 32) {
                    float wm = __ldg(&g_wpsi[m]);
                    ar = fmaf(zr, wm, ar);
                    ai = fmaf(zi, wm, ai);
                    float t1 = zi * ri;
                    float t2 = zr * ri;
                    float zN = fmaf(zr, rr, -t1);          // complex z *= r
                    zi = fmaf(zi, rr, t2);
                    zr = zN;
                    rr *= wc;                              // |r| decays by wc
                    ri *= wc;
                }
            }
            #pragma unroll
            for (int o = 16; o; o >>= 1) {
                ar += __shfl_down_sync(0xffffffffu, ar, o);
                ai += __shfl_down_sync(0xffffffffu, ai, o);
            }
            if (lane == 0) {
                float gtr = NORM_F * ar, gti = NORM_F * ai;
                float2 b = g_binned[j];
                float dr = b.x - gtr, di = b.y - gti;
                acc += dr * dr + di * di;
            }
        }
    }
    if (lane == 0) sred[warp] = acc;
    __syncthreads();

    if (tid == 0) {
        float t = sred[0] + sred[1] + sred[2] + sred[3];
        atomicAdd(&g_loss, t);
        __threadfence();
        unsigned int prev = atomicInc(&g_done, (unsigned int)(GT_BLOCKS - 1));
        if (prev == (unsigned int)(GT_BLOCKS - 1)) {
            float total = atomicAdd(&g_loss, 0.0f);   // L2-coherent read
            out[0] = sqrtf(total);
            atomicExch(&g_loss, 0.0f);                // reset for next replay
        }
    }
}

// ---------------- launch (3 kernels) ----------------
extern "C" void kernel_launch(void* const* d_in, const int* in_sizes, int n_in,
                              void* d_out, int out_size) {
    const float* fre = (const float*)d_in[0];
    const float* fim = (const float*)d_in[1];
    const float* qre = (const float*)d_in[2];
    const float* qim = (const float*)d_in[3];
    const float* pre = (const float*)d_in[4];
    const float* pim = (const float*)d_in[5];
    const float* x   = (const float*)d_in[6];
    const float* psi = (const float*)d_in[7];

    int N = in_sizes[0];
    int M = in_sizes[6];
    if (N > NMAX) N = NMAX;
    if (M > MMAX) M = MMAX;

    k_prep   <<<(N + 255) / 256, 256>>>(fre, fim, qre, qim, pre, pim, x, psi, N, M);
    k_scatter<<<(N + 255) / 256, 256>>>(N);
    k_gt_loss<<<GT_BLOCKS, 128>>>(x, (float*)d_out, M, N);
}

// round 14
// speedup vs baseline: 2.1437x; 1.1990x over previous
#include <cuda_runtime.h>
#include <math.h>

// ---------------- problem constants ----------------
#define NMAX        16384
#define MMAX        4096
#define BINS_TOTAL  65536
#define NWORDS      2048              // BINS_TOTAL / 32
#define BIN_OFFSET  24576
#define NORM_F      0.8932438417380023f   // (2/pi)^0.25
#define GT_BLOCKS   1776              // 148 SMs * 12 blocks, one wave

// ---------------- f32x2 packed helpers (FFMA2 only reachable via PTX) -------
typedef unsigned long long u64t;
__device__ __forceinline__ u64t pk2(float lo, float hi) {
    u64t r; asm("mov.b64 %0, {%1, %2};" : "=l"(r) : "f"(lo), "f"(hi)); return r;
}
__device__ __forceinline__ void upk2(u64t v, float& lo, float& hi) {
    asm("mov.b64 {%0, %1}, %2;" : "=f"(lo), "=f"(hi) : "l"(v));
}
__device__ __forceinline__ u64t fma2(u64t a, u64t b, u64t c) {
    u64t d; asm("fma.rn.f32x2 %0, %1, %2, %3;" : "=l"(d) : "l"(a), "l"(b), "l"(c)); return d;
}
__device__ __forceinline__ u64t mul2(u64t a, u64t b) {
    u64t d; asm("mul.rn.f32x2 %0, %1, %2;" : "=l"(d) : "l"(a), "l"(b)); return d;
}

// ---------------- device scratch (statically zero-initialized; each kernel
// resets what it consumed so graph replays see a clean state) ----------------
static __device__ float2   g_wpsi2[MMAX / 2]; // trapz weight * psi, pair-packed;
                                              // entries >= M stay 0 (never written)
static __device__ unsigned g_bits[NWORDS];    // presence bitmask; zeroed by k_gt_loss
static __device__ float2   g_vals[NMAX];      // pref * factors (complex)
static __device__ int      g_binoff[NMAX];
static __device__ float2   g_binned[NMAX];    // zeroed by k_prep each call
static __device__ float    g_qc[NMAX];
static __device__ float    g_pc[NMAX];
static __device__ float    g_loss;            // reset by last k_gt_loss block
static __device__ unsigned int g_done;        // atomicInc wraps -> self-resetting

// ---------------- K1: binning + prefactor + weights (all fp32, fast path) ----
__global__ void __launch_bounds__(128) k_prep(
        const float* __restrict__ fre, const float* __restrict__ fim,
        const float* __restrict__ qre, const float* __restrict__ qim,
        const float* __restrict__ pre, const float* __restrict__ pim,
        const float* __restrict__ x,   const float* __restrict__ psi,
        int N, int M) {
    int j = blockIdx.x * blockDim.x + threadIdx.x;
    if (j < M) {                              // trapz weight * psi
        float w;
        if (M < 2)           w = 0.f;
        else if (j == 0)     w = 0.5f * (x[1] - x[0]);
        else if (j == M - 1) w = 0.5f * (x[M-1] - x[M-2]);
        else                 w = 0.5f * (x[j+1] - x[j-1]);
        ((float*)g_wpsi2)[j] = w * psi[j];
    }
    if (j >= N) return;

    g_binned[j] = make_float2(0.f, 0.f);      // consumed by scatter/gt this call

    float qf = qre[j] - 0.5f * pim[j];           // Re(xi)/(2g)
    float pf = 2.0f * qim[j] + pre[j];           // Im(xi)

    // dq = 0.125 (exact), dp = 0.15625 (exact). IEEE divides so floor matches
    // jnp bit-exactly at bin boundaries (a flipped bin moves an O(100) value).
    float qb = floorf(__fdiv_rn(qf - (-8.0f),  0.125f));
    float pb = floorf(__fdiv_rn(pf - (-10.0f), 0.15625f));

    int bin = (int)(qb * 128.0f + pb);           // trunc like astype(int32)
    int off = bin + BIN_OFFSET;
    off = min(max(off, 0), BINS_TOTAL - 1);
    atomicOr(&g_bits[off >> 5], 1u << (off & 31));
    g_binoff[j] = off;

    g_qc[j] = (qb + 0.5f) * 0.125f   + (-8.0f);
    g_pc[j] = (pb + 0.5f) * 0.15625f + (-10.0f);

    // fast intrinsics: ~1e-6 rel on a clipped/continuous quantity -- well
    // inside tolerance (R10 measured 7e-7 total with this error class).
    float qi  = qim[j];
    float prf = NORM_F * __expf(qi * qi);
    float s, c;
    __sincosf(pre[j] * qi, &s, &c);
    float prRe = fminf(fmaxf(prf * c, -100.0f), 100.0f);
    float prIm = fminf(fmaxf(prf * s, -100.0f), 100.0f);

    float fr = fre[j], fi = fim[j];
    g_vals[j] = make_float2(prRe * fr - prIm * fi,
                            prRe * fi + prIm * fr);
}

// ---------------- K2: scatter-add with redundant in-block popc prefix --------
__global__ void __launch_bounds__(256) k_scatter(int N) {
    __shared__ unsigned sbits[NWORDS];
    __shared__ int      spfx[NWORDS];
    __shared__ int      wsum[8];
    const int tid  = threadIdx.x;
    const int lane = tid & 31, warp = tid >> 5;
    const unsigned FULL = 0xffffffffu;

    for (int i = tid; i < NWORDS; i += 256) sbits[i] = g_bits[i];
    __syncthreads();

    const int base = tid * 8;                 // each thread owns 8 words
    int c[8], sum = 0;
    #pragma unroll
    for (int k = 0; k < 8; k++) { c[k] = __popc(sbits[base + k]); sum += c[k]; }

    int inc = sum;                            // warp inclusive scan
    #pragma unroll
    for (int o = 1; o < 32; o <<= 1) {
        int v = __shfl_up_sync(FULL, inc, o);
        if (lane >= o) inc += v;
    }
    if (lane == 31) wsum[warp] = inc;
    __syncthreads();
    if (warp == 0 && lane < 8) {              // scan 8 warp totals
        int v = wsum[lane], i2 = v;
        #pragma unroll
        for (int o = 1; o < 8; o <<= 1) {
            int n = __shfl_up_sync(0xffu, i2, o);
            if (lane >= o) i2 += n;
        }
        wsum[lane] = i2 - v;
    }
    __syncthreads();

    int excl = inc - sum + wsum[warp];        // exclusive prefix for word base
    #pragma unroll
    for (int k = 0; k < 8; k++) { spfx[base + k] = excl; excl += c[k]; }
    __syncthreads();

    int j = blockIdx.x * 256 + tid;
    if (j >= N) return;
    int off = g_binoff[j];
    int w = off >> 5, b = off & 31;
    int ind = spfx[w] + __popc(sbits[w] & ((1u << b) - 1u));
    float2 v = g_vals[j];
    atomicAdd(&g_binned[ind].x, v.x);
    atomicAdd(&g_binned[ind].y, v.y);
}

// ---------------- K3: gt via packed-f32x2 two-point recurrence, fused loss ---
// Each lane handles grid points (m, m+1); warp stride 64. Unit rotator
// (normalized) + separate Gaussian envelope; all state in f32x2 lanes.
// 9 FMA2-pipe ops + one 8-byte load per 2 points. Zero MUFU/FP64 in the loop.
__global__ void __launch_bounds__(128) k_gt_loss(const float* __restrict__ x,
                                                 float* __restrict__ out,
                                                 int M, int N) {
    __shared__ float sred[4];
    const int tid  = threadIdx.x;
    const int warp = tid >> 5, lane = tid & 31;

    // first 16 blocks re-zero the presence bitmask for the next replay
    if (blockIdx.x < 16) g_bits[blockIdx.x * 128 + tid] = 0u;

    float acc = 0.f;
    if (M >= 2) {
        const float x0   = __ldg(&x[0]);
        const float xe   = __ldg(&x[M - 1]);
        const float h    = (xe - x0) / (float)(M - 1);  // rel err ~1e-7 (endpoints)
        const float invh = 1.0f / h;
        const float Dit  = 64.0f * h;                   // per-iteration stride
        const float D2   = Dit * Dit;
        const float twoD = 2.0f * Dit;
        const float wcs  = __expf(-2.0f * D2);
        const u64t  wc2  = pk2(wcs, wcs);

        for (int j = blockIdx.x * 4 + warp; j < N; j += GT_BLOCKS * 4) {
            const float qc = g_qc[j], pc = g_pc[j];

            // support window +-6: truncation residual exp(-36)*w*psi ~ 1e-17
            int lo = (int)((qc - 6.0f - x0) * invh);       lo = max(lo, 0);
            lo &= ~1;                                      // even: 8B-aligned pairs
            int hi = (int)((qc + 6.0f - x0) * invh) + 2;   hi = min(hi, M);

            // unit rotator for angle pc*Dit, normalized so |r|==1 exactly
            float snf, csf;
            __sincosf(pc * Dit, &snf, &csf);
            float nv = rsqrtf(fmaf(snf, snf, csf * csf));
            snf *= nv; csf *= nv;
            const u64t cs2  = pk2(csf, csf);
            const u64t sn2  = pk2(snf, snf);
            const u64t sn2n = pk2(-snf, -snf);

            u64t ar2 = 0ull, ai2 = 0ull;       // (+0.f, +0.f)
            int m0 = lo + 2 * lane;
            if (m0 < hi) {
                // inits: dx reconstructed as x0 + m*h (abs err ~3e-6, phase
                // error scales with |arg| which is only large where the
                // Gaussian is negligible)
                float tb  = x0 - qc;
                float dxa = fmaf((float)m0, h, tb);
                float dxb = dxa + h;
                float ea  = __expf(-dxa * dxa);
                float eb  = __expf(-dxb * dxb);
                float ua  = __expf(-fmaf(twoD, dxa, D2));  // envelope ratio
                float ub  = __expf(-fmaf(twoD, dxb, D2));
                float sa, ca, sb, cb;
                __sincosf(pc * dxa, &sa, &ca);
                __sincosf(pc * dxb, &sb, &cb);
                u64t zr2 = pk2(ea * ca, eb * cb);          // e*cos(theta)
                u64t yi2 = pk2(ea * sa, eb * sb);          // e*sin(theta)
                u64t u2  = pk2(ua, ub);

                for (int m = m0; m < hi; m += 64) {
                    const float2 wv = *(const float2*)((const float*)g_wpsi2 + m);
                    u64t wm2 = pk2(wv.x, wv.y);
                    ar2 = fma2(zr2, wm2, ar2);
                    ai2 = fma2(yi2, wm2, ai2);
                    u64t t1  = mul2(yi2, sn2n);            // -yi*sn
                    u64t t2  = mul2(zr2, sn2);             // +zr*sn
                    u64t zrn = fma2(zr2, cs2, t1);         // cos(theta+phi)
                    u64t yin = fma2(yi2, cs2, t2);         // sin(theta+phi)
                    zr2 = mul2(zrn, u2);                   // apply envelope
                    yi2 = mul2(yin, u2);
                    u2  = mul2(u2, wc2);                   // envelope decays
                }
            }
            float a0, a1, b0, b1;
            upk2(ar2, a0, a1); upk2(ai2, b0, b1);
            float ar = a0 + a1, ai = b0 + b1;
            #pragma unroll
            for (int o = 16; o; o >>= 1) {
                ar += __shfl_down_sync(0xffffffffu, ar, o);
                ai += __shfl_down_sync(0xffffffffu, ai, o);
            }
            if (lane == 0) {
                float gtr =  NORM_F * ar;                  // Re: sum e*cos
                float gti = -NORM_F * ai;                  // Im: conj -> -sum e*sin
                float2 b = g_binned[j];
                float dr = b.x - gtr, di = b.y - gti;
                acc += dr * dr + di * di;
            }
        }
    }
    if (lane == 0) sred[warp] = acc;
    __syncthreads();

    if (tid == 0) {
        float t = sred[0] + sred[1] + sred[2] + sred[3];
        atomicAdd(&g_loss, t);
        __threadfence();
        unsigned int prev = atomicInc(&g_done, (unsigned int)(GT_BLOCKS - 1));
        if (prev == (unsigned int)(GT_BLOCKS - 1)) {
            float total = atomicAdd(&g_loss, 0.0f);   // L2-coherent read
            out[0] = sqrtf(total);
            atomicExch(&g_loss, 0.0f);                // reset for next replay
        }
    }
}

// ---------------- launch (3 kernels) ----------------
extern "C" void kernel_launch(void* const* d_in, const int* in_sizes, int n_in,
                              void* d_out, int out_size) {
    const float* fre = (const float*)d_in[0];
    const float* fim = (const float*)d_in[1];
    const float* qre = (const float*)d_in[2];
    const float* qim = (const float*)d_in[3];
    const float* pre = (const float*)d_in[4];
    const float* pim = (const float*)d_in[5];
    const float* x   = (const float*)d_in[6];
    const float* psi = (const float*)d_in[7];

    int N = in_sizes[0];
    int M = in_sizes[6];
    if (N > NMAX) N = NMAX;
    if (M > MMAX) M = MMAX;

    int nwork = (N > M) ? N : M;
    k_prep   <<<(nwork + 127) / 128, 128>>>(fre, fim, qre, qim, pre, pim, x, psi, N, M);
    k_scatter<<<(N + 255) / 256, 256>>>(N);
    k_gt_loss<<<GT_BLOCKS, 128>>>(x, (float*)d_out, M, N);
}

// round 15
// speedup vs baseline: 2.2033x; 1.0278x over previous
#include <cuda_runtime.h>
#include <math.h>

// ---------------- problem constants ----------------
#define NMAX        16384
#define MMAX        4096
#define BINS_TOTAL  65536
#define NWORDS      2048              // BINS_TOTAL / 32
#define BIN_OFFSET  24576
#define NORM_F      0.8932438417380023f   // (2/pi)^0.25
#define GT_BLOCKS   1776              // 148 SMs * 12 blocks, one wave

// ---------------- f32x2 packed helpers (FFMA2 only reachable via PTX) -------
typedef unsigned long long u64t;
__device__ __forceinline__ u64t pk2(float lo, float hi) {
    u64t r; asm("mov.b64 %0, {%1, %2};" : "=l"(r) : "f"(lo), "f"(hi)); return r;
}
__device__ __forceinline__ void upk2(u64t v, float& lo, float& hi) {
    asm("mov.b64 {%0, %1}, %2;" : "=f"(lo), "=f"(hi) : "l"(v));
}
__device__ __forceinline__ u64t fma2(u64t a, u64t b, u64t c) {
    u64t d; asm("fma.rn.f32x2 %0, %1, %2, %3;" : "=l"(d) : "l"(a), "l"(b), "l"(c)); return d;
}
__device__ __forceinline__ u64t mul2(u64t a, u64t b) {
    u64t d; asm("mul.rn.f32x2 %0, %1, %2;" : "=l"(d) : "l"(a), "l"(b)); return d;
}

// ---------------- device scratch (statically zero-initialized; each kernel
// resets what it consumed so graph replays see a clean state) ----------------
static __device__ float2   g_wpsi2[MMAX / 2]; // trapz weight * psi, pair-packed;
                                              // entries >= M stay 0 (never written)
static __device__ unsigned g_bits[NWORDS];    // presence bitmask; zeroed by k_gt_loss
static __device__ float2   g_vals[NMAX];      // pref * factors (complex)
static __device__ int      g_binoff[NMAX];
static __device__ float2   g_binned[NMAX];    // zeroed by k_prep each call
static __device__ float    g_qc[NMAX];
static __device__ float    g_pc[NMAX];
static __device__ float    g_loss;            // reset by last k_gt_loss block
static __device__ unsigned int g_done;        // atomicInc wraps -> self-resetting

// ---------------- K1: binning + prefactor + weights --------------------------
// ALL global loads issued unconditionally up front with clamped indices so
// ptxas front-batches them (MLP ~10); the R14 profile showed this kernel
// latency-bound at occ 5.8% from serialized loads.
__global__ void __launch_bounds__(128) k_prep(
        const float* __restrict__ fre, const float* __restrict__ fim,
        const float* __restrict__ qre, const float* __restrict__ qim,
        const float* __restrict__ pre, const float* __restrict__ pim,
        const float* __restrict__ x,   const float* __restrict__ psi,
        int N, int M) {
    const int j  = blockIdx.x * 128 + threadIdx.x;
    const int jn = min(j, N - 1);
    const int jc = min(j, M - 1);
    const int jp = min(j + 1, M - 1);
    const int jm = max(j - 1, 0);

    // ---- front-batched loads (no guards: indices clamped, always valid) ----
    const float vfre = __ldg(&fre[jn]);
    const float vfim = __ldg(&fim[jn]);
    const float vqre = __ldg(&qre[jn]);
    const float vqim = __ldg(&qim[jn]);
    const float vpre = __ldg(&pre[jn]);
    const float vpim = __ldg(&pim[jn]);
    const float xc   = __ldg(&x[jc]);
    const float xp   = __ldg(&x[jp]);
    const float xm   = __ldg(&x[jm]);
    const float pv   = __ldg(&psi[jc]);

    if (j < M) {                              // trapz weight * psi
        float w;
        if (M < 2)           w = 0.f;
        else if (j == 0)     w = 0.5f * (xp - xc);
        else if (j == M - 1) w = 0.5f * (xc - xm);
        else                 w = 0.5f * (xp - xm);
        ((float*)g_wpsi2)[j] = w * pv;
    }
    if (j >= N) return;

    g_binned[j] = make_float2(0.f, 0.f);      // consumed by scatter/gt this call

    float qf = vqre - 0.5f * vpim;            // Re(xi)/(2g)
    float pf = 2.0f * vqim + vpre;            // Im(xi)

    // dq = 0.125: dividing by a power of two == multiplying by 8 EXACTLY.
    // dp = 0.15625 = 5/32: reciprocal inexact -> keep IEEE divide so floor
    // matches jnp bit-exactly (a flipped bin moves an O(100) value).
    float qb = floorf((qf + 8.0f) * 8.0f);
    float pb = floorf(__fdiv_rn(pf + 10.0f, 0.15625f));

    int bin = (int)(qb * 128.0f + pb);        // trunc like astype(int32)
    int off = bin + BIN_OFFSET;
    off = min(max(off, 0), BINS_TOTAL - 1);
    atomicOr(&g_bits[off >> 5], 1u << (off & 31));
    g_binoff[j] = off;

    g_qc[j] = (qb + 0.5f) * 0.125f   + (-8.0f);
    g_pc[j] = (pb + 0.5f) * 0.15625f + (-10.0f);

    float qi  = vqim;
    float prf = NORM_F * __expf(qi * qi);
    float s, c;
    __sincosf(vpre * qi, &s, &c);
    float prRe = fminf(fmaxf(prf * c, -100.0f), 100.0f);
    float prIm = fminf(fmaxf(prf * s, -100.0f), 100.0f);

    g_vals[j] = make_float2(prRe * vfre - prIm * vfim,
                            prRe * vfim + prIm * vfre);
}

// ---------------- K2: scatter-add with redundant in-block popc prefix --------
__global__ void __launch_bounds__(256) k_scatter(int N) {
    __shared__ unsigned sbits[NWORDS];
    __shared__ int      spfx[NWORDS];
    __shared__ int      wsum[8];
    const int tid  = threadIdx.x;
    const int lane = tid & 31, warp = tid >> 5;
    const unsigned FULL = 0xffffffffu;

    // front-batch this thread's element while the bitmask streams in
    const int j = blockIdx.x * 256 + tid;
    const int jn = min(j, N - 1);
    const int    off = __ldg(&g_binoff[jn]);
    const float2 v   = __ldg(&g_vals[jn]);

    for (int i = tid; i < NWORDS; i += 256) sbits[i] = g_bits[i];
    __syncthreads();

    const int base = tid * 8;                 // each thread owns 8 words
    int c[8], sum = 0;
    #pragma unroll
    for (int k = 0; k < 8; k++) { c[k] = __popc(sbits[base + k]); sum += c[k]; }

    int inc = sum;                            // warp inclusive scan
    #pragma unroll
    for (int o = 1; o < 32; o <<= 1) {
        int t = __shfl_up_sync(FULL, inc, o);
        if (lane >= o) inc += t;
    }
    if (lane == 31) wsum[warp] = inc;
    __syncthreads();
    if (warp == 0 && lane < 8) {              // scan 8 warp totals
        int t = wsum[lane], i2 = t;
        #pragma unroll
        for (int o = 1; o < 8; o <<= 1) {
            int n = __shfl_up_sync(0xffu, i2, o);
            if (lane >= o) i2 += n;
        }
        wsum[lane] = i2 - t;
    }
    __syncthreads();

    int excl = inc - sum + wsum[warp];        // exclusive prefix for word base
    #pragma unroll
    for (int k = 0; k < 8; k++) { spfx[base + k] = excl; excl += c[k]; }
    __syncthreads();

    if (j >= N) return;
    int w = off >> 5, b = off & 31;
    int ind = spfx[w] + __popc(sbits[w] & ((1u << b) - 1u));
    atomicAdd(&g_binned[ind].x, v.x);
    atomicAdd(&g_binned[ind].y, v.y);
}

// ---------------- K3: gt via packed-f32x2 combined recurrence, fused loss ----
// Each lane handles grid points (m, m+1); warp stride 64. Combined state:
// Z = e*(cos,sin), R = u*(cos phi, sin phi); step: Z *= R, R *= wc.
// 8 FMA-pipe ops + sign-XOR on ALU pipe per 2 points. Zero MUFU/FP64 in loop.
__global__ void __launch_bounds__(128) k_gt_loss(const float* __restrict__ x,
                                                 float* __restrict__ out,
                                                 int M, int N) {
    __shared__ float sred[4];
    const int tid  = threadIdx.x;
    const int warp = tid >> 5, lane = tid & 31;

    // first 16 blocks re-zero the presence bitmask for the next replay
    if (blockIdx.x < 16) g_bits[blockIdx.x * 128 + tid] = 0u;

    float acc = 0.f;
    if (M >= 2) {
        const float x0   = __ldg(&x[0]);
        const float h    = (__ldg(&x[M - 1]) - x0) / (float)(M - 1);
        const float invh = 1.0f / h;
        const float Dit  = 64.0f * h;                   // per-iteration stride
        const float D2   = Dit * Dit;
        const float twoD = 2.0f * Dit;
        const float wcs  = __expf(-2.0f * D2);
        const u64t  wc2  = pk2(wcs, wcs);
        const float uhb  = __expf(-twoD * h);           // ub/ua (const)
        const u64t  SGN  = 0x8000000080000000ull;

        for (int j = blockIdx.x * 4 + warp; j < N; j += GT_BLOCKS * 4) {
            const float qc = __ldg(&g_qc[j]), pc = __ldg(&g_pc[j]);

            // support window +-4: omitted mass erfc(4)*h ~ 1e-8 abs in gt
            int lo = (int)((qc - 4.0f - x0) * invh);       lo = max(lo, 0);
            lo &= ~1;                                      // even: 8B-aligned pairs
            int hi = (int)((qc + 4.0f - x0) * invh) + 2;   hi = min(hi, M);

            u64t ar2 = 0ull, ai2 = 0ull;
            int m0 = lo + 2 * lane;
            if (m0 < hi) {
                float dxa = fmaf((float)m0, h, x0 - qc);
                float dxb = dxa + h;
                float ea  = __expf(-dxa * dxa);
                float eb  = __expf(-dxb * dxb);
                float ua  = __expf(-fmaf(twoD, dxa, D2));  // envelope ratio
                float ub  = ua * uhb;
                float sa, ca;
                __sincosf(pc * dxa, &sa, &ca);
                float sh_, ch_;                            // warp-uniform
                __sincosf(pc * h, &sh_, &ch_);
                float cb = ca * ch_ - sa * sh_;            // rotate by pc*h
                float sb = sa * ch_ + ca * sh_;
                float sD, cD;                              // warp-uniform
                __sincosf(pc * Dit, &sD, &cD);

                u64t zr2 = pk2(ea * ca, eb * cb);          // e*cos(theta)
                u64t zi2 = pk2(ea * sa, eb * sb);          // e*sin(theta)
                u64t rr2 = pk2(ua * cD, ub * cD);          // u*cos(phi)
                u64t ri2 = pk2(ua * sD, ub * sD);          // u*sin(phi)

                for (int m = m0; m < hi; m += 64) {
                    const float2 wv = *(const float2*)((const float*)g_wpsi2 + m);
                    u64t wm2 = pk2(wv.x, wv.y);
                    ar2 = fma2(zr2, wm2, ar2);
                    ai2 = fma2(zi2, wm2, ai2);
                    u64t rin = ri2 ^ SGN;                  // -Ri (ALU pipe)
                    u64t t1  = mul2(zi2, rin);
                    u64t t2  = mul2(zr2, ri2);
                    u64t zrn = fma2(zr2, rr2, t1);         // Z *= R
                    zi2 = fma2(zi2, rr2, t2);
                    zr2 = zrn;
                    rr2 = mul2(rr2, wc2);                  // R *= wc
                    ri2 = mul2(ri2, wc2);
                }
            }
            float a0, a1, b0, b1;
            upk2(ar2, a0, a1); upk2(ai2, b0, b1);
            float ar = a0 + a1, ai = b0 + b1;
            #pragma unroll
            for (int o = 16; o; o >>= 1) {
                ar += __shfl_down_sync(0xffffffffu, ar, o);
                ai += __shfl_down_sync(0xffffffffu, ai, o);
            }
            if (lane == 0) {
                float gtr =  NORM_F * ar;                  // Re: sum e*cos
                float gti = -NORM_F * ai;                  // Im: conj -> -sum e*sin
                float2 b = g_binned[j];
                float dr = b.x - gtr, di = b.y - gti;
                acc += dr * dr + di * di;
            }
        }
    }
    if (lane == 0) sred[warp] = acc;
    __syncthreads();

    if (tid == 0) {
        float t = sred[0] + sred[1] + sred[2] + sred[3];
        atomicAdd(&g_loss, t);
        __threadfence();
        unsigned int prev = atomicInc(&g_done, (unsigned int)(GT_BLOCKS - 1));
        if (prev == (unsigned int)(GT_BLOCKS - 1)) {
            float total = atomicAdd(&g_loss, 0.0f);   // L2-coherent read
            out[0] = sqrtf(total);
            atomicExch(&g_loss, 0.0f);                // reset for next replay
        }
    }
}

// ---------------- launch (3 kernels) ----------------
extern "C" void kernel_launch(void* const* d_in, const int* in_sizes, int n_in,
                              void* d_out, int out_size) {
    const float* fre = (const float*)d_in[0];
    const float* fim = (const float*)d_in[1];
    const float* qre = (const float*)d_in[2];
    const float* qim = (const float*)d_in[3];
    const float* pre = (const float*)d_in[4];
    const float* pim = (const float*)d_in[5];
    const float* x   = (const float*)d_in[6];
    const float* psi = (const float*)d_in[7];

    int N = in_sizes[0];
    int M = in_sizes[6];
    if (N > NMAX) N = NMAX;
    if (M > MMAX) M = MMAX;

    int nwork = (N > M) ? N : M;
    k_prep   <<<(nwork + 127) / 128, 128>>>(fre, fim, qre, qim, pre, pim, x, psi, N, M);
    k_scatter<<<(N + 255) / 256, 256>>>(N);
    k_gt_loss<<<GT_BLOCKS, 128>>>(x, (float*)d_out, M, N);
}